// round 15
// baseline (speedup 1.0000x reference)
#include <cuda_runtime.h>
#include <cuda_fp16.h>
#include <math.h>
#include <stdint.h>

#define S    2048
#define H    8
#define D    64
#define NB   2
#define EMB  512
#define BQB  128           // q-rows per attn block
#define NTB  (S/BQB)       // 16 q-blocks per (n,h)
#define NTJ  (S/64)        // 32 j-tiles
#define KP   72            // halves pad (144B rows: ldmatrix conflict-free)
#define VP   72
#define PP   72
#define EP   72
#define ZP   72
#define KTILE (64*KP)
#define ERING 256          // E ring rows (4 chunks of 64)
// K pre-scale folds softmax 1/sqrt(512) AND log2(e) so p = exp2(score).
#define KSCALE 0.06376737214440946f   // (1/sqrt(512)) * log2(e)
#define VSPLIT 8           // vsum splits per (n,h)

// Scratch (allocation-free rule: __device__ globals)
__device__ __half g_qh[NB*H*S*D];
__device__ __half g_kh[NB*H*S*D];    // pre-scaled by KSCALE
__device__ __half g_vh[NB*H*S*D];
__device__ __half g_eh[S*D];
__device__ __half g_wo[EMB*EMB];
__device__ __half g_z [NB*S*EMB];
__device__ float  g_racc[NB*S*EMB];
__device__ float  g_vpart[NB*H*VSPLIT*D];

// ---------------------------------------------------------------------------
// helpers
// ---------------------------------------------------------------------------
__device__ __forceinline__ uint32_t h2u(float a, float b) {
    __half2 h = __floats2half2_rn(a, b);
    return *reinterpret_cast<uint32_t*>(&h);
}

__device__ __forceinline__ void mma16(float c[4],
                                      uint32_t a0, uint32_t a1, uint32_t a2, uint32_t a3,
                                      uint32_t b0, uint32_t b1)
{
    asm volatile(
        "mma.sync.aligned.m16n8k16.row.col.f32.f16.f16.f32 "
        "{%0,%1,%2,%3}, {%4,%5,%6,%7}, {%8,%9}, {%0,%1,%2,%3};"
        : "+f"(c[0]), "+f"(c[1]), "+f"(c[2]), "+f"(c[3])
        : "r"(a0), "r"(a1), "r"(a2), "r"(a3), "r"(b0), "r"(b1));
}

__device__ __forceinline__ void ldsm4(uint32_t r[4], const __half* p) {
    uint32_t a = (uint32_t)__cvta_generic_to_shared(p);
    asm volatile("ldmatrix.sync.aligned.m8n8.x4.shared.b16 {%0,%1,%2,%3}, [%4];"
        : "=r"(r[0]), "=r"(r[1]), "=r"(r[2]), "=r"(r[3]) : "r"(a));
}
__device__ __forceinline__ void ldsm4t(uint32_t r[4], const __half* p) {
    uint32_t a = (uint32_t)__cvta_generic_to_shared(p);
    asm volatile("ldmatrix.sync.aligned.m8n8.x4.trans.shared.b16 {%0,%1,%2,%3}, [%4];"
        : "=r"(r[0]), "=r"(r[1]), "=r"(r[2]), "=r"(r[3]) : "r"(a));
}

__device__ __forceinline__ void cpa16(__half* dst, const __half* src) {
    uint32_t d = (uint32_t)__cvta_generic_to_shared(dst);
    asm volatile("cp.async.cg.shared.global [%0], [%1], 16;" :: "r"(d), "l"(src));
}
__device__ __forceinline__ void cpa16z(__half* dst, const __half* src, int sz) {
    uint32_t d = (uint32_t)__cvta_generic_to_shared(dst);
    asm volatile("cp.async.cg.shared.global [%0], [%1], 16, %2;"
                 :: "r"(d), "l"(src), "r"(sz));
}
#define CP_COMMIT() asm volatile("cp.async.commit_group;")
#define CP_WAIT1()  asm volatile("cp.async.wait_group 1;")

// ---------------------------------------------------------------------------
// Kernel 0: one-time fp16 conversions (E and Wo fused into one launch)
// ---------------------------------------------------------------------------
#define NE4 (S*D/4)          // 32768 float4's in E
#define NW4 (EMB*EMB/4)      // 65536 float4's in Wo
__global__ __launch_bounds__(256)
void conv_kernel(const float* __restrict__ E, const float* __restrict__ Wo)
{
    int i = blockIdx.x * blockDim.x + threadIdx.x;
    if (i < NE4) {
        float4 x = reinterpret_cast<const float4*>(E)[i];
        uint2 u; u.x = h2u(x.x, x.y); u.y = h2u(x.z, x.w);
        reinterpret_cast<uint2*>(g_eh)[i] = u;
    } else {
        int j = i - NE4;
        float4 x = reinterpret_cast<const float4*>(Wo)[j];
        uint2 u; u.x = h2u(x.x, x.y); u.y = h2u(x.z, x.w);
        reinterpret_cast<uint2*>(g_wo)[j] = u;
    }
}

// ---------------------------------------------------------------------------
// Kernel 1: per-head projections on fp16 tensor cores.
// 128 X-rows per block (2 s-tiles share one W tile), 256 thr / 8 warps.
// K output pre-scaled by KSCALE (softmax scale + log2e fold).
// ---------------------------------------------------------------------------
__global__ __launch_bounds__(256)
void proj_kernel(const float* __restrict__ q, const float* __restrict__ k,
                 const float* __restrict__ v,
                 const float* __restrict__ Wq, const float* __restrict__ bq,
                 const float* __restrict__ Wk, const float* __restrict__ bk,
                 const float* __restrict__ Wv, const float* __restrict__ bv)
{
    __shared__ __half Xs[128*ZP];  // X tile [s][e]
    __shared__ __half Ws[64*ZP];   // W tile [d][e]

    int which = blockIdx.y;
    const float* X = (which == 0) ? q  : (which == 1) ? k  : v;
    const float* W = (which == 0) ? Wq : (which == 1) ? Wk : Wv;
    const float* b = (which == 0) ? bq : (which == 1) ? bk : bv;
    __half*    Out = (which == 0) ? g_qh : (which == 1) ? g_kh : g_vh;
    const float scale = (which == 1) ? KSCALE : 1.0f;

    int bid = blockIdx.x;
    int st  = bid % (S/128);
    int h   = (bid / (S/128)) % H;
    int n   = bid / ((S/128) * H);
    int s0  = st * 128;
    int tid  = threadIdx.x;
    int lane = tid & 31;
    int wr   = tid >> 5;
    int lq   = lane >> 2;
    int lr   = lane & 3;
    int g8   = lane >> 3;
    int i8   = lane & 7;

    const int ar = (g8 & 1)*8 + i8;     // A ldmatrix row
    const int ac = (g8 >> 1)*8;
    const int nr = (g8 >> 1)*8 + i8;    // B ldmatrix row
    const int nc = (g8 & 1)*8;

    // stage X (128x64) with fp32->fp16 conversion
    for (int t = tid; t < 128*16; t += 256) {
        int r = t >> 4, e4 = (t & 15) * 4;
        float4 x = *reinterpret_cast<const float4*>(X + (size_t)(n*S + s0 + r)*EMB + h*D + e4);
        uint2 ux; ux.x = h2u(x.x, x.y); ux.y = h2u(x.z, x.w);
        *reinterpret_cast<uint2*>(Xs + r*ZP + e4) = ux;
    }
    // stage W (64x64)
    for (int t = tid; t < 64*16; t += 256) {
        int r = t >> 4, e4 = (t & 15) * 4;
        float4 w = *reinterpret_cast<const float4*>(W + (size_t)r*D + e4);
        uint2 uw; uw.x = h2u(w.x, w.y); uw.y = h2u(w.z, w.w);
        *reinterpret_cast<uint2*>(Ws + r*ZP + e4) = uw;
    }
    __syncthreads();

    float acc[8][4];
#pragma unroll
    for (int nt = 0; nt < 8; nt++)
#pragma unroll
        for (int i = 0; i < 4; i++) acc[nt][i] = 0.f;

#pragma unroll
    for (int ks = 0; ks < 4; ks++) {
        uint32_t av[4];
        ldsm4(av, Xs + (wr*16 + ar)*ZP + ks*16 + ac);
#pragma unroll
        for (int nt2 = 0; nt2 < 4; nt2++) {
            uint32_t bb[4];
            ldsm4(bb, Ws + (nt2*16 + nr)*ZP + ks*16 + nc);
            mma16(acc[2*nt2],   av[0], av[1], av[2], av[3], bb[0], bb[1]);
            mma16(acc[2*nt2+1], av[0], av[1], av[2], av[3], bb[2], bb[3]);
        }
    }

    int row = s0 + wr*16 + lq;
    __half* op0 = Out + ((size_t)(n*H + h)*S + row)*D;
    __half* op1 = op0 + 8*D;
#pragma unroll
    for (int nt = 0; nt < 8; nt++) {
        int col = nt*8 + 2*lr;
        float2 bb = *reinterpret_cast<const float2*>(b + col);
        uint32_t lo = h2u((acc[nt][0] + bb.x)*scale, (acc[nt][1] + bb.y)*scale);
        uint32_t hi = h2u((acc[nt][2] + bb.x)*scale, (acc[nt][3] + bb.y)*scale);
        *reinterpret_cast<uint32_t*>(op0 + col) = lo;
        *reinterpret_cast<uint32_t*>(op1 + col) = hi;
    }
}

// ---------------------------------------------------------------------------
// attn staging helpers (256 threads)
// ---------------------------------------------------------------------------
__device__ __forceinline__ void stage_kv(
    int jt, int tid, int q0,
    const __half* Kh, const __half* Vh, __half* Ksm, __half* Vsm)
{
    int j0 = jt * 64, buf = jt & 1;
    {
        __half* Vd = Vsm + buf*KTILE;
        const __half* src = Vh + (size_t)j0*D;
#pragma unroll
        for (int t = tid; t < 512; t += 256) {
            int r = t >> 3, c = t & 7;
            cpa16(Vd + r*VP + c*8, src + r*D + c*8);
        }
    }
    if (j0 >= q0) {
        __half* Kd = Ksm + buf*KTILE;
        const __half* src = Kh + (size_t)j0*D;
#pragma unroll
        for (int t = tid; t < 512; t += 256) {
            int r = t >> 3, c = t & 7;
            cpa16(Kd + r*KP + c*8, src + r*D + c*8);
        }
    }
}

__device__ __forceinline__ void stage_e(int c, int tid, int l_origin, __half* Esm)
{
    int slot = (c & 3) * 64;
#pragma unroll
    for (int t = tid; t < 512; t += 256) {
        int r = t >> 3, cc = t & 7;
        int l = l_origin + c*64 + r;
        const __half* src = (l < S) ? (g_eh + (size_t)l*D + cc*8) : g_eh;
        cpa16z(Esm + (slot + r)*EP + cc*8, src, (l < S) ? 16 : 0);
    }
}

// ---------------------------------------------------------------------------
// Kernel 2: fused attention (wait1 -> sync -> compute -> sync). BQ=128,
// 256 threads / 8 warps. Fixed-max softmax with exp2 (log2e folded into K),
// softmax-denominator shuffles deferred to the epilogue, diagonal-tile-only
// masking, R->P accumulator register recycling via g_racc.
// Row S-1's uniform-softmax part is added by vsum_fin afterwards.
// ---------------------------------------------------------------------------
__global__ __launch_bounds__(256, 2)
void attn_kernel()
{
    extern __shared__ __half smh[];
    __half* Ksm = smh;                     // 2 x [64][KP]
    __half* Vsm = Ksm + 2*KTILE;           // 2 x [64][VP]
    __half* Esm = Vsm + 2*KTILE;           // [256][EP] ring (4 chunks)
    __half* Psh = Esm + ERING*EP;          // [128][PP]

    int bid = blockIdx.x;
    int qtb = bid % NTB;
    int h   = (bid / NTB) % H;
    int n   = bid / (NTB * H);
    int q0  = qtb * BQB;
    int tid  = threadIdx.x;
    int lane = tid & 31;
    int wr   = tid >> 5;
    int lq   = lane >> 2;
    int lr   = lane & 3;
    int g8   = lane >> 3;
    int i8   = lane & 7;

    const int nr = (g8 >> 1)*8 + i8;    // non-trans B row
    const int nc = (g8 & 1)*8;          // non-trans B col
    const int jr = (g8 & 1)*8 + i8;     // trans (V) row
    const int dc = (g8 >> 1)*8;         // trans (V) col
    const int ar = (g8 & 1)*8 + i8;     // A row (Psh)
    const int ac = (g8 >> 1)*8;         // A col

    const __half* Qh = g_qh + (size_t)(n*H + h)*S*D;
    const __half* Kh = g_kh + (size_t)(n*H + h)*S*D;
    const __half* Vh = g_vh + (size_t)(n*H + h)*S*D;

    const int grpB  = (wr >= 4);
    const int q0w   = q0 + grpB*64;        // warp's 64-row tile base
    const int qtw   = q0w >> 6;            // transition j-tile
    const int w16   = (wr & 3) * 16;
    const int rloc  = w16 + lq;            // row local to warp's 64-group
    const int rblk  = wr*16 + lq;          // row local to 128-block
    const int ilo   = q0 + rblk;           // global row (and +8)
    const int l_origin = S - 128 - q0;
    const int bandlo = 48 - w16, bandhi = 126 - w16;

    // Q fragments, resident
    uint32_t qa[4][4];
#pragma unroll
    for (int ks = 0; ks < 4; ks++) {
        const __half* qb = Qh + (size_t)ilo*D + ks*16 + 2*lr;
        qa[ks][0] = *reinterpret_cast<const uint32_t*>(qb);
        qa[ks][1] = *reinterpret_cast<const uint32_t*>(qb + 8*D);
        qa[ks][2] = *reinterpret_cast<const uint32_t*>(qb + 8);
        qa[ks][3] = *reinterpret_cast<const uint32_t*>(qb + 8*D + 8);
    }

    float acc[8][4];
#pragma unroll
    for (int nt = 0; nt < 8; nt++)
#pragma unroll
        for (int i = 0; i < 4; i++) acc[nt][i] = 0.f;

    float s0 = 0.f, s1 = 0.f;   // lane-local partials; reduced in epilogue

    // ---- pipeline prologue: tile 0 K/V + E chunks 0,1,2 ----
    stage_kv(0, tid, q0, Kh, Vh, Ksm, Vsm);
    stage_e(0, tid, l_origin, Esm);
    stage_e(1, tid, l_origin, Esm);
    stage_e(2, tid, l_origin, Esm);
    CP_COMMIT();

    for (int jt = 0; jt < NTJ; jt++) {
        int j0 = jt * 64;

        if (jt + 1 < NTJ) {
            stage_kv(jt + 1, tid, q0, Kh, Vh, Ksm, Vsm);
            if (jt < 2*qtb) stage_e(jt + 3, tid, l_origin, Esm);  // max chunk read = 2qtb+2
        }
        CP_COMMIT();
        CP_WAIT1();
        __syncthreads();   // tile jt data visible to all threads

        const __half* Kt = Ksm + (jt & 1)*KTILE;
        const __half* Vt = Vsm + (jt & 1)*KTILE;

        // ================= doR (first: transition spill precedes doP) ======
        if (j0 <= q0w) {
            int bc   = jt + 1 - grpB;          // base E chunk for this warp
            int dq   = q0w - j0;
            int base = (bc & 3) * 64;

#pragma unroll
            for (int cb = 0; cb < 8; cb++) {
                if (cb*16 + 15 < bandlo || cb*16 > bandhi) continue;
                int rowb = base + cb*16; if (rowb >= ERING) rowb -= ERING;
                float qeA[4] = {0.f,0.f,0.f,0.f};
                float qeB[4] = {0.f,0.f,0.f,0.f};
#pragma unroll
                for (int ks = 0; ks < 4; ks++) {
                    uint32_t b[4];
                    ldsm4(b, Esm + (rowb + nr)*EP + ks*16 + nc);
                    mma16(qeA, qa[ks][0], qa[ks][1], qa[ks][2], qa[ks][3], b[0], b[1]);
                    mma16(qeB, qa[ks][0], qa[ks][1], qa[ks][2], qa[ks][3], b[2], b[3]);
                }
#pragma unroll
                for (int hb = 0; hb < 2; hb++) {
                    float* qv = hb ? qeB : qeA;
                    int rr  = cb*16 + hb*8 + 2*lr;
                    int cjA = rr - 63 + rloc;
                    int cjB = cjA + 8;
                    if (cjA >= 0 && cjA < 64)
                        Psh[rblk*PP + cjA] =
                            __float2half((cjA <= dq + rloc) ? qv[0] : 0.f);
                    if (cjA + 1 >= 0 && cjA + 1 < 64)
                        Psh[rblk*PP + cjA + 1] =
                            __float2half((cjA + 1 <= dq + rloc) ? qv[1] : 0.f);
                    if (cjB >= 0 && cjB < 64)
                        Psh[(rblk + 8)*PP + cjB] =
                            __float2half((cjB <= dq + rloc + 8) ? qv[2] : 0.f);
                    if (cjB + 1 >= 0 && cjB + 1 < 64)
                        Psh[(rblk + 8)*PP + cjB + 1] =
                            __float2half((cjB + 1 <= dq + rloc + 8) ? qv[3] : 0.f);
                }
            }
            __syncwarp();

            // acc += R @ V
#pragma unroll
            for (int ksv = 0; ksv < 4; ksv++) {
                uint32_t av[4];
                ldsm4(av, Psh + (wr*16 + ar)*PP + ksv*16 + ac);
#pragma unroll
                for (int nt2 = 0; nt2 < 4; nt2++) {
                    uint32_t b[4];
                    ldsm4t(b, Vt + (ksv*16 + jr)*VP + nt2*16 + dc);
                    mma16(acc[2*nt2],   av[0], av[1], av[2], av[3], b[0], b[1]);
                    mma16(acc[2*nt2+1], av[0], av[1], av[2], av[3], b[2], b[3]);
                }
            }
            // (no trailing __syncwarp: two __syncthreads separate this read
            //  from the next tile's Psh scatter, and barriers imply warp sync)

            if (jt == qtw) {
                // spill finished R-part, recycle registers for P-part
                float* rp0 = g_racc + ((size_t)n*S + ilo    )*EMB + h*D;
                float* rp1 = g_racc + ((size_t)n*S + ilo + 8)*EMB + h*D;
#pragma unroll
                for (int nt = 0; nt < 8; nt++) {
                    int col = nt*8 + 2*lr;
                    *reinterpret_cast<float2*>(rp0 + col) =
                        make_float2(acc[nt][0], acc[nt][1]);
                    *reinterpret_cast<float2*>(rp1 + col) =
                        make_float2(acc[nt][2], acc[nt][3]);
                    acc[nt][0] = 0.f; acc[nt][1] = 0.f;
                    acc[nt][2] = 0.f; acc[nt][3] = 0.f;
                }
            }
        }

        // ================= doP =============================================
        if (j0 >= q0w) {
            float sc[8][4];
#pragma unroll
            for (int nt = 0; nt < 8; nt++)
#pragma unroll
                for (int i = 0; i < 4; i++) sc[nt][i] = 0.f;
#pragma unroll
            for (int ks = 0; ks < 4; ks++) {
#pragma unroll
                for (int nt2 = 0; nt2 < 4; nt2++) {
                    uint32_t b[4];
                    ldsm4(b, Kt + (nt2*16 + nr)*KP + ks*16 + nc);
                    mma16(sc[2*nt2],   qa[ks][0], qa[ks][1], qa[ks][2], qa[ks][3], b[0], b[1]);
                    mma16(sc[2*nt2+1], qa[ks][0], qa[ks][1], qa[ks][2], qa[ks][3], b[2], b[3]);
                }
            }

            // mask only on the diagonal tile (all later tiles fully unmasked)
            if (j0 == q0w) {
#pragma unroll
                for (int nt = 0; nt < 8; nt++) {
                    int jc = j0 + nt*8 + 2*lr;
                    if (jc     <= ilo    ) sc[nt][0] = -INFINITY;
                    if (jc + 1 <= ilo    ) sc[nt][1] = -INFINITY;
                    if (jc     <= ilo + 8) sc[nt][2] = -INFINITY;
                    if (jc + 1 <= ilo + 8) sc[nt][3] = -INFINITY;
                }
            }

            // fixed-max softmax: p = exp2(score) (log2e folded into K scale);
            // denominators accumulate lane-locally, reduced once in epilogue.
            uint32_t ph0[8], ph1[8];
#pragma unroll
            for (int nt = 0; nt < 8; nt++) {
                float p0 = exp2f(sc[nt][0]);
                float p1 = exp2f(sc[nt][1]);
                float p2 = exp2f(sc[nt][2]);
                float p3 = exp2f(sc[nt][3]);
                s0 += p0 + p1;  s1 += p2 + p3;
                ph0[nt] = h2u(p0, p1);
                ph1[nt] = h2u(p2, p3);
            }

            // acc += P @ V (P from registers)
#pragma unroll
            for (int ksv = 0; ksv < 4; ksv++) {
                uint32_t a0 = ph0[2*ksv],   a1 = ph1[2*ksv];
                uint32_t a2 = ph0[2*ksv+1], a3 = ph1[2*ksv+1];
#pragma unroll
                for (int nt2 = 0; nt2 < 4; nt2++) {
                    uint32_t b[4];
                    ldsm4t(b, Vt + (ksv*16 + jr)*VP + nt2*16 + dc);
                    mma16(acc[2*nt2],   a0, a1, a2, a3, b[0], b[1]);
                    mma16(acc[2*nt2+1], a0, a1, a2, a3, b[2], b[3]);
                }
            }
        }

        __syncthreads();   // all warps done with cur buffers before overwrite
    }

    // ---- epilogue: reduce denominators once; z = P/s + R (R from g_racc);
    //      row S-1 P-part zeroed ----
    s0 += __shfl_xor_sync(0xffffffffu, s0, 1);
    s0 += __shfl_xor_sync(0xffffffffu, s0, 2);
    s1 += __shfl_xor_sync(0xffffffffu, s1, 1);
    s1 += __shfl_xor_sync(0xffffffffu, s1, 2);
    float f0 = (ilo     == S-1) ? 0.f : 1.0f / s0;
    float f1 = (ilo + 8 == S-1) ? 0.f : 1.0f / s1;
    const float* rp0 = g_racc + ((size_t)n*S + ilo    )*EMB + h*D;
    const float* rp1 = g_racc + ((size_t)n*S + ilo + 8)*EMB + h*D;
#pragma unroll
    for (int nt = 0; nt < 8; nt++) {
        int col = nt*8 + 2*lr;
        float2 r0 = *reinterpret_cast<const float2*>(rp0 + col);
        float2 r1 = *reinterpret_cast<const float2*>(rp1 + col);
        uint32_t lo = h2u(acc[nt][0]*f0 + r0.x, acc[nt][1]*f0 + r0.y);
        uint32_t hi = h2u(acc[nt][2]*f1 + r1.x, acc[nt][3]*f1 + r1.y);
        *reinterpret_cast<uint32_t*>(g_z + ((size_t)n*S + ilo    )*EMB + h*D + col) = lo;
        *reinterpret_cast<uint32_t*>(g_z + ((size_t)n*S + ilo + 8)*EMB + h*D + col) = hi;
    }
}

// ---------------------------------------------------------------------------
// Kernel 2b: row S-1 uniform-softmax part, two-phase.
// ---------------------------------------------------------------------------
__global__ __launch_bounds__(256)
void vsum_part_kernel()
{
    __shared__ float sums[256];
    int blk   = blockIdx.x;          // nh*VSPLIT + split
    int nh    = blk / VSPLIT;
    int split = blk % VSPLIT;
    int tid = threadIdx.x;
    int d    = tid & 63;
    int part = tid >> 6;             // 4 parts x 64 rows
    const __half* Vp = g_vh + (size_t)nh*S*D
                     + ((size_t)split*256 + (size_t)part*64)*D + d;

    float s = 0.f;
#pragma unroll 1
    for (int j = 0; j < 64; j += 8) {
        float t0 = __half2float(Vp[(j+0)*D]);
        float t1 = __half2float(Vp[(j+1)*D]);
        float t2 = __half2float(Vp[(j+2)*D]);
        float t3 = __half2float(Vp[(j+3)*D]);
        float t4 = __half2float(Vp[(j+4)*D]);
        float t5 = __half2float(Vp[(j+5)*D]);
        float t6 = __half2float(Vp[(j+6)*D]);
        float t7 = __half2float(Vp[(j+7)*D]);
        s += ((t0 + t1) + (t2 + t3)) + ((t4 + t5) + (t6 + t7));
    }
    sums[tid] = s;
    __syncthreads();

    if (tid < 64) {
        float t = sums[tid] + sums[tid+64] + sums[tid+128] + sums[tid+192];
        g_vpart[(size_t)blk*D + tid] = t;
    }
}

__global__ __launch_bounds__(64)
void vsum_fin_kernel()
{
    int nh = blockIdx.x;
    int d  = threadIdx.x;
    float t = 0.f;
#pragma unroll
    for (int p = 0; p < VSPLIT; p++)
        t += g_vpart[((size_t)nh*VSPLIT + p)*D + d];
    int n = nh / H, h = nh % H;
    __half* zp = g_z + ((size_t)n*S + (S-1))*EMB + h*D + d;
    *zp = __float2half(__half2float(*zp) + t * (1.0f / (float)S));
}

// ---------------------------------------------------------------------------
// Kernel 3: out = z @ Wo.T + bo — fp16 tensor cores, cp.async k-pipeline,
// two-barrier pattern (wait1 -> sync -> compute -> sync).
// ---------------------------------------------------------------------------
__global__ __launch_bounds__(256)
void outproj_kernel(const float* __restrict__ bo, float* __restrict__ out)
{
    extern __shared__ __half smo[];
    __half* Zs = smo;                    // 2 x [128][ZP]
    __half* Ws = smo + 2*128*ZP;         // 2 x [64][ZP]

    int r0  = blockIdx.x * 128;
    int d0  = blockIdx.y * 64;
    int tid  = threadIdx.x;
    int lane = tid & 31;
    int wr   = tid >> 5;
    int lq   = lane >> 2;
    int lr   = lane & 3;
    int g8   = lane >> 3;
    int i8   = lane & 7;

    const int ar = (g8 & 1)*8 + i8;
    const int ac = (g8 >> 1)*8;
    const int nr = (g8 >> 1)*8 + i8;
    const int nc = (g8 & 1)*8;

    float acc[8][4];
#pragma unroll
    for (int nt = 0; nt < 8; nt++)
#pragma unroll
        for (int i = 0; i < 4; i++) acc[nt][i] = 0.f;

    auto stage = [&](int kc) {
        int buf = kc & 1;
        int e0  = kc * 64;
        __half* Zd = Zs + buf*128*ZP;
        __half* Wd = Ws + buf*64*ZP;
#pragma unroll
        for (int t = tid; t < 1024; t += 256) {
            int r = t >> 3, c = t & 7;
            cpa16(Zd + r*ZP + c*8, g_z + (size_t)(r0 + r)*EMB + e0 + c*8);
        }
#pragma unroll
        for (int t = tid; t < 512; t += 256) {
            int r = t >> 3, c = t & 7;
            cpa16(Wd + r*ZP + c*8, g_wo + (size_t)(d0 + r)*EMB + e0 + c*8);
        }
    };

    stage(0);
    CP_COMMIT();

    for (int kc = 0; kc < 8; kc++) {
        if (kc + 1 < 8) stage(kc + 1);
        CP_COMMIT();
        CP_WAIT1();
        __syncthreads();   // chunk kc visible to all threads

        const __half* Zb = Zs + (kc & 1)*128*ZP;
        const __half* Wb = Ws + (kc & 1)*64*ZP;

#pragma unroll
        for (int ks = 0; ks < 4; ks++) {
            uint32_t av[4];
            ldsm4(av, Zb + (wr*16 + ar)*ZP + ks*16 + ac);
#pragma unroll
            for (int nt2 = 0; nt2 < 4; nt2++) {
                uint32_t b[4];
                ldsm4(b, Wb + (nt2*16 + nr)*ZP + ks*16 + nc);
                mma16(acc[2*nt2],   av[0], av[1], av[2], av[3], b[0], b[1]);
                mma16(acc[2*nt2+1], av[0], av[1], av[2], av[3], b[2], b[3]);
            }
        }
        __syncthreads();   // reads done before next overwrite of this buffer
    }

    int row = r0 + wr*16 + lq;
#pragma unroll
    for (int nt = 0; nt < 8; nt++) {
        int col = d0 + nt*8 + 2*lr;
        float2 bb = *reinterpret_cast<const float2*>(bo + col);
        float2 lo = make_float2(acc[nt][0] + bb.x, acc[nt][1] + bb.y);
        float2 hi = make_float2(acc[nt][2] + bb.x, acc[nt][3] + bb.y);
        *reinterpret_cast<float2*>(out + (size_t)row*EMB + col) = lo;
        *reinterpret_cast<float2*>(out + (size_t)(row + 8)*EMB + col) = hi;
    }
}

// ---------------------------------------------------------------------------
extern "C" void kernel_launch(void* const* d_in, const int* in_sizes, int n_in,
                              void* d_out, int out_size)
{
    const float* v  = (const float*)d_in[0];
    const float* k  = (const float*)d_in[1];
    const float* q  = (const float*)d_in[2];
    const float* Wv = (const float*)d_in[3];
    const float* bv = (const float*)d_in[4];
    const float* Wk = (const float*)d_in[5];
    const float* bk = (const float*)d_in[6];
    const float* Wq = (const float*)d_in[7];
    const float* bq = (const float*)d_in[8];
    const float* E  = (const float*)d_in[9];
    const float* Wo = (const float*)d_in[10];
    const float* bo = (const float*)d_in[11];
    float* out = (float*)d_out;

    conv_kernel<<<(NE4 + NW4)/256, 256>>>(E, Wo);

    dim3 gp(NB*H*(S/128), 3);
    proj_kernel<<<gp, 256>>>(q, k, v, Wq, bq, Wk, bk, Wv, bv);

    vsum_part_kernel<<<NB*H*VSPLIT, 256>>>();

    size_t smem = (size_t)(2*KTILE + 2*KTILE + ERING*EP + 128*PP) * sizeof(__half);
    cudaFuncSetAttribute(attn_kernel,
                         cudaFuncAttributeMaxDynamicSharedMemorySize,
                         (int)smem);
    attn_kernel<<<NB*H*NTB, 256, smem>>>();

    vsum_fin_kernel<<<NB*H, 64>>>();

    size_t smemo = (size_t)(2*128*ZP + 2*64*ZP) * sizeof(__half);
    cudaFuncSetAttribute(outproj_kernel,
                         cudaFuncAttributeMaxDynamicSharedMemorySize,
                         (int)smemo);
    dim3 go(NB*S/128, EMB/64);
    outproj_kernel<<<go, 256, smemo>>>(bo, out);
}

// round 16
// speedup vs baseline: 1.0147x; 1.0147x over previous
#include <cuda_runtime.h>
#include <cuda_fp16.h>
#include <math.h>
#include <stdint.h>

#define S    2048
#define H    8
#define D    64
#define NB   2
#define EMB  512
#define BQB  128           // q-rows per attn block
#define NTB  (S/BQB)       // 16 q-blocks per (n,h)
#define NTJ  (S/64)        // 32 j-tiles
#define KP   72            // halves pad (144B rows: ldmatrix conflict-free)
#define VP   72
#define PP   72
#define EP   72
#define ZP   72
#define KTILE (64*KP)
#define ERING 256          // E ring rows (4 chunks of 64)
// K pre-scale folds softmax 1/sqrt(512) AND log2(e) so p = exp2(score).
#define KSCALE 0.06376737214440946f   // (1/sqrt(512)) * log2(e)
#define VSPLIT 8           // vsum splits per (n,h)

// Scratch (allocation-free rule: __device__ globals)
__device__ __half g_qh[NB*H*S*D];
__device__ __half g_kh[NB*H*S*D];    // pre-scaled by KSCALE
__device__ __half g_vh[NB*H*S*D];
__device__ __half g_eh[S*D];
__device__ __half g_wo[EMB*EMB];
__device__ __half g_z [NB*S*EMB];
__device__ float  g_racc[NB*S*EMB];
__device__ float  g_vpart[NB*H*VSPLIT*D];

// ---------------------------------------------------------------------------
// helpers
// ---------------------------------------------------------------------------
__device__ __forceinline__ uint32_t h2u(float a, float b) {
    __half2 h = __floats2half2_rn(a, b);
    return *reinterpret_cast<uint32_t*>(&h);
}

__device__ __forceinline__ void mma16(float c[4],
                                      uint32_t a0, uint32_t a1, uint32_t a2, uint32_t a3,
                                      uint32_t b0, uint32_t b1)
{
    asm volatile(
        "mma.sync.aligned.m16n8k16.row.col.f32.f16.f16.f32 "
        "{%0,%1,%2,%3}, {%4,%5,%6,%7}, {%8,%9}, {%0,%1,%2,%3};"
        : "+f"(c[0]), "+f"(c[1]), "+f"(c[2]), "+f"(c[3])
        : "r"(a0), "r"(a1), "r"(a2), "r"(a3), "r"(b0), "r"(b1));
}

__device__ __forceinline__ void ldsm4(uint32_t r[4], const __half* p) {
    uint32_t a = (uint32_t)__cvta_generic_to_shared(p);
    asm volatile("ldmatrix.sync.aligned.m8n8.x4.shared.b16 {%0,%1,%2,%3}, [%4];"
        : "=r"(r[0]), "=r"(r[1]), "=r"(r[2]), "=r"(r[3]) : "r"(a));
}
__device__ __forceinline__ void ldsm4t(uint32_t r[4], const __half* p) {
    uint32_t a = (uint32_t)__cvta_generic_to_shared(p);
    asm volatile("ldmatrix.sync.aligned.m8n8.x4.trans.shared.b16 {%0,%1,%2,%3}, [%4];"
        : "=r"(r[0]), "=r"(r[1]), "=r"(r[2]), "=r"(r[3]) : "r"(a));
}

__device__ __forceinline__ void cpa16(__half* dst, const __half* src) {
    uint32_t d = (uint32_t)__cvta_generic_to_shared(dst);
    asm volatile("cp.async.cg.shared.global [%0], [%1], 16;" :: "r"(d), "l"(src));
}
__device__ __forceinline__ void cpa16z(__half* dst, const __half* src, int sz) {
    uint32_t d = (uint32_t)__cvta_generic_to_shared(dst);
    asm volatile("cp.async.cg.shared.global [%0], [%1], 16, %2;"
                 :: "r"(d), "l"(src), "r"(sz));
}
#define CP_COMMIT() asm volatile("cp.async.commit_group;")
#define CP_WAIT1()  asm volatile("cp.async.wait_group 1;")

#define NE4 (S*D/4)          // 32768 float4's in E
#define NW4 (EMB*EMB/4)      // 65536 float4's in Wo

// ---------------------------------------------------------------------------
// Kernel 1: per-head projections on fp16 tensor cores (+ fused E/Wo convert
// on grid.y==3). 128 X-rows per block, 256 thr / 8 warps.
// K output pre-scaled by KSCALE (softmax scale + log2e fold).
// ---------------------------------------------------------------------------
__global__ __launch_bounds__(256)
void proj_kernel(const float* __restrict__ q, const float* __restrict__ k,
                 const float* __restrict__ v,
                 const float* __restrict__ Wq, const float* __restrict__ bq,
                 const float* __restrict__ Wk, const float* __restrict__ bk,
                 const float* __restrict__ Wv, const float* __restrict__ bv,
                 const float* __restrict__ E,  const float* __restrict__ Wo)
{
    __shared__ __half Xs[128*ZP];  // X tile [s][e]
    __shared__ __half Ws[64*ZP];   // W tile [d][e]

    int which = blockIdx.y;
    if (which == 3) {
        // fused one-time conversions: E -> g_eh, Wo -> g_wo
        for (int i = blockIdx.x * 256 + threadIdx.x; i < NE4 + NW4; i += 256*256) {
            if (i < NE4) {
                float4 x = reinterpret_cast<const float4*>(E)[i];
                uint2 u; u.x = h2u(x.x, x.y); u.y = h2u(x.z, x.w);
                reinterpret_cast<uint2*>(g_eh)[i] = u;
            } else {
                int j = i - NE4;
                float4 x = reinterpret_cast<const float4*>(Wo)[j];
                uint2 u; u.x = h2u(x.x, x.y); u.y = h2u(x.z, x.w);
                reinterpret_cast<uint2*>(g_wo)[j] = u;
            }
        }
        return;
    }

    const float* X = (which == 0) ? q  : (which == 1) ? k  : v;
    const float* W = (which == 0) ? Wq : (which == 1) ? Wk : Wv;
    const float* b = (which == 0) ? bq : (which == 1) ? bk : bv;
    __half*    Out = (which == 0) ? g_qh : (which == 1) ? g_kh : g_vh;
    const float scale = (which == 1) ? KSCALE : 1.0f;

    int bid = blockIdx.x;
    int st  = bid % (S/128);
    int h   = (bid / (S/128)) % H;
    int n   = bid / ((S/128) * H);
    int s0  = st * 128;
    int tid  = threadIdx.x;
    int lane = tid & 31;
    int wr   = tid >> 5;
    int lq   = lane >> 2;
    int lr   = lane & 3;
    int g8   = lane >> 3;
    int i8   = lane & 7;

    const int ar = (g8 & 1)*8 + i8;     // A ldmatrix row
    const int ac = (g8 >> 1)*8;
    const int nr = (g8 >> 1)*8 + i8;    // B ldmatrix row
    const int nc = (g8 & 1)*8;

    for (int t = tid; t < 128*16; t += 256) {
        int r = t >> 4, e4 = (t & 15) * 4;
        float4 x = *reinterpret_cast<const float4*>(X + (size_t)(n*S + s0 + r)*EMB + h*D + e4);
        uint2 ux; ux.x = h2u(x.x, x.y); ux.y = h2u(x.z, x.w);
        *reinterpret_cast<uint2*>(Xs + r*ZP + e4) = ux;
    }
    for (int t = tid; t < 64*16; t += 256) {
        int r = t >> 4, e4 = (t & 15) * 4;
        float4 w = *reinterpret_cast<const float4*>(W + (size_t)r*D + e4);
        uint2 uw; uw.x = h2u(w.x, w.y); uw.y = h2u(w.z, w.w);
        *reinterpret_cast<uint2*>(Ws + r*ZP + e4) = uw;
    }
    __syncthreads();

    float acc[8][4];
#pragma unroll
    for (int nt = 0; nt < 8; nt++)
#pragma unroll
        for (int i = 0; i < 4; i++) acc[nt][i] = 0.f;

#pragma unroll
    for (int ks = 0; ks < 4; ks++) {
        uint32_t av[4];
        ldsm4(av, Xs + (wr*16 + ar)*ZP + ks*16 + ac);
#pragma unroll
        for (int nt2 = 0; nt2 < 4; nt2++) {
            uint32_t bb[4];
            ldsm4(bb, Ws + (nt2*16 + nr)*ZP + ks*16 + nc);
            mma16(acc[2*nt2],   av[0], av[1], av[2], av[3], bb[0], bb[1]);
            mma16(acc[2*nt2+1], av[0], av[1], av[2], av[3], bb[2], bb[3]);
        }
    }

    int row = s0 + wr*16 + lq;
    __half* op0 = Out + ((size_t)(n*H + h)*S + row)*D;
    __half* op1 = op0 + 8*D;
#pragma unroll
    for (int nt = 0; nt < 8; nt++) {
        int col = nt*8 + 2*lr;
        float2 bb = *reinterpret_cast<const float2*>(b + col);
        uint32_t lo = h2u((acc[nt][0] + bb.x)*scale, (acc[nt][1] + bb.y)*scale);
        uint32_t hi = h2u((acc[nt][2] + bb.x)*scale, (acc[nt][3] + bb.y)*scale);
        *reinterpret_cast<uint32_t*>(op0 + col) = lo;
        *reinterpret_cast<uint32_t*>(op1 + col) = hi;
    }
}

// ---------------------------------------------------------------------------
// attn staging helpers (256 threads)
// ---------------------------------------------------------------------------
__device__ __forceinline__ void stage_kv(
    int jt, int tid, int q0,
    const __half* Kh, const __half* Vh, __half* Ksm, __half* Vsm)
{
    int j0 = jt * 64, buf = jt & 1;
    {
        __half* Vd = Vsm + buf*KTILE;
        const __half* src = Vh + (size_t)j0*D;
#pragma unroll
        for (int t = tid; t < 512; t += 256) {
            int r = t >> 3, c = t & 7;
            cpa16(Vd + r*VP + c*8, src + r*D + c*8);
        }
    }
    if (j0 >= q0) {
        __half* Kd = Ksm + buf*KTILE;
        const __half* src = Kh + (size_t)j0*D;
#pragma unroll
        for (int t = tid; t < 512; t += 256) {
            int r = t >> 3, c = t & 7;
            cpa16(Kd + r*KP + c*8, src + r*D + c*8);
        }
    }
}

__device__ __forceinline__ void stage_e(int c, int tid, int l_origin, __half* Esm)
{
    int slot = (c & 3) * 64;
#pragma unroll
    for (int t = tid; t < 512; t += 256) {
        int r = t >> 3, cc = t & 7;
        int l = l_origin + c*64 + r;
        const __half* src = (l < S) ? (g_eh + (size_t)l*D + cc*8) : g_eh;
        cpa16z(Esm + (slot + r)*EP + cc*8, src, (l < S) ? 16 : 0);
    }
}

// ---------------------------------------------------------------------------
// Kernel 2: fused attention. All MMA loops manually software-pipelined
// (volatile asm pins order, so overlap must be hand-scheduled): iteration i
// issues ldmatrix for i+1 before the MMAs of i; PV's first V fragment is
// issued before the exp2 block. Accumulation order is bit-identical to R15.
// ---------------------------------------------------------------------------
__global__ __launch_bounds__(256, 2)
void attn_kernel()
{
    extern __shared__ __half smh[];
    __half* Ksm = smh;                     // 2 x [64][KP]
    __half* Vsm = Ksm + 2*KTILE;           // 2 x [64][VP]
    __half* Esm = Vsm + 2*KTILE;           // [256][EP] ring (4 chunks)
    __half* Psh = Esm + ERING*EP;          // [128][PP]

    int bid = blockIdx.x;
    int qtb = bid % NTB;
    int h   = (bid / NTB) % H;
    int n   = bid / (NTB * H);
    int q0  = qtb * BQB;
    int tid  = threadIdx.x;
    int lane = tid & 31;
    int wr   = tid >> 5;
    int lq   = lane >> 2;
    int lr   = lane & 3;
    int g8   = lane >> 3;
    int i8   = lane & 7;

    const int nr = (g8 >> 1)*8 + i8;    // non-trans B row
    const int nc = (g8 & 1)*8;          // non-trans B col
    const int jr = (g8 & 1)*8 + i8;     // trans (V) row
    const int dc = (g8 >> 1)*8;         // trans (V) col
    const int ar = (g8 & 1)*8 + i8;     // A row (Psh)
    const int ac = (g8 >> 1)*8;         // A col

    const __half* Qh = g_qh + (size_t)(n*H + h)*S*D;
    const __half* Kh = g_kh + (size_t)(n*H + h)*S*D;
    const __half* Vh = g_vh + (size_t)(n*H + h)*S*D;

    const int grpB  = (wr >= 4);
    const int q0w   = q0 + grpB*64;        // warp's 64-row tile base
    const int qtw   = q0w >> 6;            // transition j-tile
    const int w16   = (wr & 3) * 16;
    const int rloc  = w16 + lq;            // row local to warp's 64-group
    const int rblk  = wr*16 + lq;          // row local to 128-block
    const int ilo   = q0 + rblk;           // global row (and +8)
    const int l_origin = S - 128 - q0;
    const int bandlo = 48 - w16, bandhi = 126 - w16;

    // Q fragments, resident
    uint32_t qa[4][4];
#pragma unroll
    for (int ks = 0; ks < 4; ks++) {
        const __half* qb = Qh + (size_t)ilo*D + ks*16 + 2*lr;
        qa[ks][0] = *reinterpret_cast<const uint32_t*>(qb);
        qa[ks][1] = *reinterpret_cast<const uint32_t*>(qb + 8*D);
        qa[ks][2] = *reinterpret_cast<const uint32_t*>(qb + 8);
        qa[ks][3] = *reinterpret_cast<const uint32_t*>(qb + 8*D + 8);
    }

    float acc[8][4];
#pragma unroll
    for (int nt = 0; nt < 8; nt++)
#pragma unroll
        for (int i = 0; i < 4; i++) acc[nt][i] = 0.f;

    float s0 = 0.f, s1 = 0.f;   // lane-local partials; reduced in epilogue

    // ---- pipeline prologue: tile 0 K/V + E chunks 0,1,2 ----
    stage_kv(0, tid, q0, Kh, Vh, Ksm, Vsm);
    stage_e(0, tid, l_origin, Esm);
    stage_e(1, tid, l_origin, Esm);
    stage_e(2, tid, l_origin, Esm);
    CP_COMMIT();

    for (int jt = 0; jt < NTJ; jt++) {
        int j0 = jt * 64;

        if (jt + 1 < NTJ) {
            stage_kv(jt + 1, tid, q0, Kh, Vh, Ksm, Vsm);
            if (jt < 2*qtb) stage_e(jt + 3, tid, l_origin, Esm);
        }
        CP_COMMIT();
        CP_WAIT1();
        __syncthreads();   // tile jt data visible to all threads

        const __half* Kt = Ksm + (jt & 1)*KTILE;
        const __half* Vt = Vsm + (jt & 1)*KTILE;

        // ================= doR (first: transition spill precedes doP) ======
        if (j0 <= q0w) {
            int bc   = jt + 1 - grpB;          // base E chunk for this warp
            int dq   = q0w - j0;
            int base = (bc & 3) * 64;

#pragma unroll
            for (int cb = 0; cb < 8; cb++) {
                if (cb*16 + 15 < bandlo || cb*16 > bandhi) continue;
                int rowb = base + cb*16; if (rowb >= ERING) rowb -= ERING;
                const __half* Eb = Esm + (rowb + nr)*EP + nc;
                float qeA[4] = {0.f,0.f,0.f,0.f};
                float qeB[4] = {0.f,0.f,0.f,0.f};
                uint32_t eb[2][4];
                ldsm4(eb[0], Eb);
#pragma unroll
                for (int ks = 0; ks < 4; ks++) {
                    if (ks < 3) ldsm4(eb[(ks+1)&1], Eb + (ks+1)*16);
                    mma16(qeA, qa[ks][0], qa[ks][1], qa[ks][2], qa[ks][3],
                          eb[ks&1][0], eb[ks&1][1]);
                    mma16(qeB, qa[ks][0], qa[ks][1], qa[ks][2], qa[ks][3],
                          eb[ks&1][2], eb[ks&1][3]);
                }
#pragma unroll
                for (int hb = 0; hb < 2; hb++) {
                    float* qv = hb ? qeB : qeA;
                    int rr  = cb*16 + hb*8 + 2*lr;
                    int cjA = rr - 63 + rloc;
                    int cjB = cjA + 8;
                    if (cjA >= 0 && cjA < 64)
                        Psh[rblk*PP + cjA] =
                            __float2half((cjA <= dq + rloc) ? qv[0] : 0.f);
                    if (cjA + 1 >= 0 && cjA + 1 < 64)
                        Psh[rblk*PP + cjA + 1] =
                            __float2half((cjA + 1 <= dq + rloc) ? qv[1] : 0.f);
                    if (cjB >= 0 && cjB < 64)
                        Psh[(rblk + 8)*PP + cjB] =
                            __float2half((cjB <= dq + rloc + 8) ? qv[2] : 0.f);
                    if (cjB + 1 >= 0 && cjB + 1 < 64)
                        Psh[(rblk + 8)*PP + cjB + 1] =
                            __float2half((cjB + 1 <= dq + rloc + 8) ? qv[3] : 0.f);
                }
            }
            __syncwarp();

            // acc += R @ V  (pipelined: av per ksv, b double-buffered)
            {
                const __half* Pb = Psh + (wr*16 + ar)*PP + ac;
                uint32_t av[2][4], rb[2][4];
                ldsm4(av[0], Pb);
                ldsm4t(rb[0], Vt + jr*VP + dc);
#pragma unroll
                for (int i = 0; i < 16; i++) {
                    int ksv = i >> 2, nt2 = i & 3;
                    if (i < 15) {
                        int j = i + 1;
                        ldsm4t(rb[j & 1],
                               Vt + ((j >> 2)*16 + jr)*VP + (j & 3)*16 + dc);
                    }
                    if (nt2 == 0 && ksv < 3)
                        ldsm4(av[(ksv + 1) & 1], Pb + (ksv + 1)*16);
                    uint32_t* a = av[ksv & 1];
                    mma16(acc[2*nt2],   a[0], a[1], a[2], a[3],
                          rb[i&1][0], rb[i&1][1]);
                    mma16(acc[2*nt2+1], a[0], a[1], a[2], a[3],
                          rb[i&1][2], rb[i&1][3]);
                }
            }

            if (jt == qtw) {
                // spill finished R-part, recycle registers for P-part
                float* rp0 = g_racc + ((size_t)n*S + ilo    )*EMB + h*D;
                float* rp1 = g_racc + ((size_t)n*S + ilo + 8)*EMB + h*D;
#pragma unroll
                for (int nt = 0; nt < 8; nt++) {
                    int col = nt*8 + 2*lr;
                    *reinterpret_cast<float2*>(rp0 + col) =
                        make_float2(acc[nt][0], acc[nt][1]);
                    *reinterpret_cast<float2*>(rp1 + col) =
                        make_float2(acc[nt][2], acc[nt][3]);
                    acc[nt][0] = 0.f; acc[nt][1] = 0.f;
                    acc[nt][2] = 0.f; acc[nt][3] = 0.f;
                }
            }
        }

        // ================= doP =============================================
        if (j0 >= q0w) {
            // ---- scores (pipelined ldsm->mma) ----
            float sc[8][4];
#pragma unroll
            for (int nt = 0; nt < 8; nt++)
#pragma unroll
                for (int i = 0; i < 4; i++) sc[nt][i] = 0.f;
            {
                uint32_t kb[2][4];
                ldsm4(kb[0], Kt + nr*KP + nc);
#pragma unroll
                for (int i = 0; i < 16; i++) {
                    int ks = i >> 2, nt2 = i & 3;
                    if (i < 15) {
                        int j = i + 1;
                        ldsm4(kb[j & 1],
                              Kt + ((j & 3)*16 + nr)*KP + (j >> 2)*16 + nc);
                    }
                    mma16(sc[2*nt2],   qa[ks][0], qa[ks][1], qa[ks][2], qa[ks][3],
                          kb[i&1][0], kb[i&1][1]);
                    mma16(sc[2*nt2+1], qa[ks][0], qa[ks][1], qa[ks][2], qa[ks][3],
                          kb[i&1][2], kb[i&1][3]);
                }
            }

            // mask only on the diagonal tile
            if (j0 == q0w) {
#pragma unroll
                for (int nt = 0; nt < 8; nt++) {
                    int jc = j0 + nt*8 + 2*lr;
                    if (jc     <= ilo    ) sc[nt][0] = -INFINITY;
                    if (jc + 1 <= ilo    ) sc[nt][1] = -INFINITY;
                    if (jc     <= ilo + 8) sc[nt][2] = -INFINITY;
                    if (jc + 1 <= ilo + 8) sc[nt][3] = -INFINITY;
                }
            }

            // issue first V fragment BEFORE the exp2 chain (overlap LDS/MUFU)
            uint32_t vb[2][4];
            ldsm4t(vb[0], Vt + jr*VP + dc);

            // fixed-max softmax: p = exp2(score); lane-local denominators
            uint32_t ph0[8], ph1[8];
#pragma unroll
            for (int nt = 0; nt < 8; nt++) {
                float p0 = exp2f(sc[nt][0]);
                float p1 = exp2f(sc[nt][1]);
                float p2 = exp2f(sc[nt][2]);
                float p3 = exp2f(sc[nt][3]);
                s0 += p0 + p1;  s1 += p2 + p3;
                ph0[nt] = h2u(p0, p1);
                ph1[nt] = h2u(p2, p3);
            }

            // acc += P @ V (P from registers; V pipelined)
#pragma unroll
            for (int i = 0; i < 16; i++) {
                int ksv = i >> 2, nt2 = i & 3;
                if (i < 15) {
                    int j = i + 1;
                    ldsm4t(vb[j & 1],
                           Vt + ((j >> 2)*16 + jr)*VP + (j & 3)*16 + dc);
                }
                uint32_t a0 = ph0[2*ksv],   a1 = ph1[2*ksv];
                uint32_t a2 = ph0[2*ksv+1], a3 = ph1[2*ksv+1];
                mma16(acc[2*nt2],   a0, a1, a2, a3, vb[i&1][0], vb[i&1][1]);
                mma16(acc[2*nt2+1], a0, a1, a2, a3, vb[i&1][2], vb[i&1][3]);
            }
        }

        __syncthreads();   // all warps done with cur buffers before overwrite
    }

    // ---- epilogue ----
    s0 += __shfl_xor_sync(0xffffffffu, s0, 1);
    s0 += __shfl_xor_sync(0xffffffffu, s0, 2);
    s1 += __shfl_xor_sync(0xffffffffu, s1, 1);
    s1 += __shfl_xor_sync(0xffffffffu, s1, 2);
    float f0 = (ilo     == S-1) ? 0.f : 1.0f / s0;
    float f1 = (ilo + 8 == S-1) ? 0.f : 1.0f / s1;
    const float* rp0 = g_racc + ((size_t)n*S + ilo    )*EMB + h*D;
    const float* rp1 = g_racc + ((size_t)n*S + ilo + 8)*EMB + h*D;
#pragma unroll
    for (int nt = 0; nt < 8; nt++) {
        int col = nt*8 + 2*lr;
        float2 r0 = *reinterpret_cast<const float2*>(rp0 + col);
        float2 r1 = *reinterpret_cast<const float2*>(rp1 + col);
        uint32_t lo = h2u(acc[nt][0]*f0 + r0.x, acc[nt][1]*f0 + r0.y);
        uint32_t hi = h2u(acc[nt][2]*f1 + r1.x, acc[nt][3]*f1 + r1.y);
        *reinterpret_cast<uint32_t*>(g_z + ((size_t)n*S + ilo    )*EMB + h*D + col) = lo;
        *reinterpret_cast<uint32_t*>(g_z + ((size_t)n*S + ilo + 8)*EMB + h*D + col) = hi;
    }
}

// ---------------------------------------------------------------------------
// Kernel 2b: row S-1 uniform-softmax part, two-phase.
// ---------------------------------------------------------------------------
__global__ __launch_bounds__(256)
void vsum_part_kernel()
{
    __shared__ float sums[256];
    int blk   = blockIdx.x;          // nh*VSPLIT + split
    int nh    = blk / VSPLIT;
    int split = blk % VSPLIT;
    int tid = threadIdx.x;
    int d    = tid & 63;
    int part = tid >> 6;             // 4 parts x 64 rows
    const __half* Vp = g_vh + (size_t)nh*S*D
                     + ((size_t)split*256 + (size_t)part*64)*D + d;

    float s = 0.f;
#pragma unroll 1
    for (int j = 0; j < 64; j += 8) {
        float t0 = __half2float(Vp[(j+0)*D]);
        float t1 = __half2float(Vp[(j+1)*D]);
        float t2 = __half2float(Vp[(j+2)*D]);
        float t3 = __half2float(Vp[(j+3)*D]);
        float t4 = __half2float(Vp[(j+4)*D]);
        float t5 = __half2float(Vp[(j+5)*D]);
        float t6 = __half2float(Vp[(j+6)*D]);
        float t7 = __half2float(Vp[(j+7)*D]);
        s += ((t0 + t1) + (t2 + t3)) + ((t4 + t5) + (t6 + t7));
    }
    sums[tid] = s;
    __syncthreads();

    if (tid < 64) {
        float t = sums[tid] + sums[tid+64] + sums[tid+128] + sums[tid+192];
        g_vpart[(size_t)blk*D + tid] = t;
    }
}

__global__ __launch_bounds__(64)
void vsum_fin_kernel()
{
    int nh = blockIdx.x;
    int d  = threadIdx.x;
    float t = 0.f;
#pragma unroll
    for (int p = 0; p < VSPLIT; p++)
        t += g_vpart[((size_t)nh*VSPLIT + p)*D + d];
    int n = nh / H, h = nh % H;
    __half* zp = g_z + ((size_t)n*S + (S-1))*EMB + h*D + d;
    *zp = __float2half(__half2float(*zp) + t * (1.0f / (float)S));
}

// ---------------------------------------------------------------------------
// Kernel 3: out = z @ Wo.T + bo — fp16 tensor cores, cp.async k-pipeline.
// ---------------------------------------------------------------------------
__global__ __launch_bounds__(256)
void outproj_kernel(const float* __restrict__ bo, float* __restrict__ out)
{
    extern __shared__ __half smo[];
    __half* Zs = smo;                    // 2 x [128][ZP]
    __half* Ws = smo + 2*128*ZP;         // 2 x [64][ZP]

    int r0  = blockIdx.x * 128;
    int d0  = blockIdx.y * 64;
    int tid  = threadIdx.x;
    int lane = tid & 31;
    int wr   = tid >> 5;
    int lq   = lane >> 2;
    int lr   = lane & 3;
    int g8   = lane >> 3;
    int i8   = lane & 7;

    const int ar = (g8 & 1)*8 + i8;
    const int ac = (g8 >> 1)*8;
    const int nr = (g8 >> 1)*8 + i8;
    const int nc = (g8 & 1)*8;

    float acc[8][4];
#pragma unroll
    for (int nt = 0; nt < 8; nt++)
#pragma unroll
        for (int i = 0; i < 4; i++) acc[nt][i] = 0.f;

    auto stage = [&](int kc) {
        int buf = kc & 1;
        int e0  = kc * 64;
        __half* Zd = Zs + buf*128*ZP;
        __half* Wd = Ws + buf*64*ZP;
#pragma unroll
        for (int t = tid; t < 1024; t += 256) {
            int r = t >> 3, c = t & 7;
            cpa16(Zd + r*ZP + c*8, g_z + (size_t)(r0 + r)*EMB + e0 + c*8);
        }
#pragma unroll
        for (int t = tid; t < 512; t += 256) {
            int r = t >> 3, c = t & 7;
            cpa16(Wd + r*ZP + c*8, g_wo + (size_t)(d0 + r)*EMB + e0 + c*8);
        }
    };

    stage(0);
    CP_COMMIT();

    for (int kc = 0; kc < 8; kc++) {
        if (kc + 1 < 8) stage(kc + 1);
        CP_COMMIT();
        CP_WAIT1();
        __syncthreads();

        const __half* Zb = Zs + (kc & 1)*128*ZP;
        const __half* Wb = Ws + (kc & 1)*64*ZP;

#pragma unroll
        for (int ks = 0; ks < 4; ks++) {
            uint32_t av[4];
            ldsm4(av, Zb + (wr*16 + ar)*ZP + ks*16 + ac);
#pragma unroll
            for (int nt2 = 0; nt2 < 4; nt2++) {
                uint32_t b[4];
                ldsm4(b, Wb + (nt2*16 + nr)*ZP + ks*16 + nc);
                mma16(acc[2*nt2],   av[0], av[1], av[2], av[3], b[0], b[1]);
                mma16(acc[2*nt2+1], av[0], av[1], av[2], av[3], b[2], b[3]);
            }
        }
        __syncthreads();
    }

    int row = r0 + wr*16 + lq;
#pragma unroll
    for (int nt = 0; nt < 8; nt++) {
        int col = d0 + nt*8 + 2*lr;
        float2 bb = *reinterpret_cast<const float2*>(bo + col);
        float2 lo = make_float2(acc[nt][0] + bb.x, acc[nt][1] + bb.y);
        float2 hi = make_float2(acc[nt][2] + bb.x, acc[nt][3] + bb.y);
        *reinterpret_cast<float2*>(out + (size_t)row*EMB + col) = lo;
        *reinterpret_cast<float2*>(out + (size_t)(row + 8)*EMB + col) = hi;
    }
}

// ---------------------------------------------------------------------------
extern "C" void kernel_launch(void* const* d_in, const int* in_sizes, int n_in,
                              void* d_out, int out_size)
{
    const float* v  = (const float*)d_in[0];
    const float* k  = (const float*)d_in[1];
    const float* q  = (const float*)d_in[2];
    const float* Wv = (const float*)d_in[3];
    const float* bv = (const float*)d_in[4];
    const float* Wk = (const float*)d_in[5];
    const float* bk = (const float*)d_in[6];
    const float* Wq = (const float*)d_in[7];
    const float* bq = (const float*)d_in[8];
    const float* E  = (const float*)d_in[9];
    const float* Wo = (const float*)d_in[10];
    const float* bo = (const float*)d_in[11];
    float* out = (float*)d_out;

    dim3 gp(NB*H*(S/128), 4);   // y=0..2: q/k/v proj, y=3: E/Wo convert
    proj_kernel<<<gp, 256>>>(q, k, v, Wq, bq, Wk, bk, Wv, bv, E, Wo);

    vsum_part_kernel<<<NB*H*VSPLIT, 256>>>();

    size_t smem = (size_t)(2*KTILE + 2*KTILE + ERING*EP + 128*PP) * sizeof(__half);
    cudaFuncSetAttribute(attn_kernel,
                         cudaFuncAttributeMaxDynamicSharedMemorySize,
                         (int)smem);
    attn_kernel<<<NB*H*NTB, 256, smem>>>();

    vsum_fin_kernel<<<NB*H, 64>>>();

    size_t smemo = (size_t)(2*128*ZP + 2*64*ZP) * sizeof(__half);
    cudaFuncSetAttribute(outproj_kernel,
                         cudaFuncAttributeMaxDynamicSharedMemorySize,
                         (int)smemo);
    dim3 go(NB*S/128, EMB/64);
    outproj_kernel<<<go, 256, smemo>>>(bo, out);
}

// round 17
// speedup vs baseline: 1.0167x; 1.0019x over previous
#include <cuda_runtime.h>
#include <cuda_fp16.h>
#include <math.h>
#include <stdint.h>

#define S    2048
#define H    8
#define D    64
#define NB   2
#define EMB  512
#define BQB  128           // q-rows per attn block
#define NTB  (S/BQB)       // 16 q-blocks per (n,h)
#define NTJ  (S/64)        // 32 j-tiles
#define KP   72            // halves pad (144B rows: ldmatrix conflict-free)
#define VP   72
#define PP   72
#define EP   72
#define ZP   72
#define KTILE (64*KP)
#define ERING 256          // E ring rows (4 chunks of 64)
// K pre-scale folds softmax 1/sqrt(512) AND log2(e) so p = exp2(score).
#define KSCALE 0.06376737214440946f   // (1/sqrt(512)) * log2(e)
#define VSPLIT 8           // vsum splits per (n,h)

// Scratch (allocation-free rule: __device__ globals)
__device__ __half g_qh[NB*H*S*D];
__device__ __half g_kh[NB*H*S*D];    // pre-scaled by KSCALE
__device__ __half g_vh[NB*H*S*D];
__device__ __half g_eh[S*D];
__device__ __half g_wo[EMB*EMB];
__device__ __half g_z [NB*S*EMB];
__device__ float  g_racc[NB*S*EMB];
__device__ float  g_vpart[NB*H*VSPLIT*D];

// ---------------------------------------------------------------------------
// helpers
// ---------------------------------------------------------------------------
__device__ __forceinline__ uint32_t h2u(float a, float b) {
    __half2 h = __floats2half2_rn(a, b);
    return *reinterpret_cast<uint32_t*>(&h);
}

__device__ __forceinline__ void mma16(float c[4],
                                      uint32_t a0, uint32_t a1, uint32_t a2, uint32_t a3,
                                      uint32_t b0, uint32_t b1)
{
    asm volatile(
        "mma.sync.aligned.m16n8k16.row.col.f32.f16.f16.f32 "
        "{%0,%1,%2,%3}, {%4,%5,%6,%7}, {%8,%9}, {%0,%1,%2,%3};"
        : "+f"(c[0]), "+f"(c[1]), "+f"(c[2]), "+f"(c[3])
        : "r"(a0), "r"(a1), "r"(a2), "r"(a3), "r"(b0), "r"(b1));
}

__device__ __forceinline__ void ldsm4(uint32_t r[4], const __half* p) {
    uint32_t a = (uint32_t)__cvta_generic_to_shared(p);
    asm volatile("ldmatrix.sync.aligned.m8n8.x4.shared.b16 {%0,%1,%2,%3}, [%4];"
        : "=r"(r[0]), "=r"(r[1]), "=r"(r[2]), "=r"(r[3]) : "r"(a));
}
__device__ __forceinline__ void ldsm4t(uint32_t r[4], const __half* p) {
    uint32_t a = (uint32_t)__cvta_generic_to_shared(p);
    asm volatile("ldmatrix.sync.aligned.m8n8.x4.trans.shared.b16 {%0,%1,%2,%3}, [%4];"
        : "=r"(r[0]), "=r"(r[1]), "=r"(r[2]), "=r"(r[3]) : "r"(a));
}

__device__ __forceinline__ void cpa16(__half* dst, const __half* src) {
    uint32_t d = (uint32_t)__cvta_generic_to_shared(dst);
    asm volatile("cp.async.cg.shared.global [%0], [%1], 16;" :: "r"(d), "l"(src));
}
__device__ __forceinline__ void cpa16z(__half* dst, const __half* src, int sz) {
    uint32_t d = (uint32_t)__cvta_generic_to_shared(dst);
    asm volatile("cp.async.cg.shared.global [%0], [%1], 16, %2;"
                 :: "r"(d), "l"(src), "r"(sz));
}
#define CP_COMMIT() asm volatile("cp.async.commit_group;")
#define CP_WAIT1()  asm volatile("cp.async.wait_group 1;")

#define NE4 (S*D/4)          // 32768 float4's in E
#define NW4 (EMB*EMB/4)      // 65536 float4's in Wo

// ---------------------------------------------------------------------------
// Kernel 1: per-head projections on fp16 tensor cores (+ fused E/Wo convert
// on grid.y==3). 128 X-rows per block, 256 thr / 8 warps.
// K output pre-scaled by KSCALE (softmax scale + log2e fold).
// ---------------------------------------------------------------------------
__global__ __launch_bounds__(256)
void proj_kernel(const float* __restrict__ q, const float* __restrict__ k,
                 const float* __restrict__ v,
                 const float* __restrict__ Wq, const float* __restrict__ bq,
                 const float* __restrict__ Wk, const float* __restrict__ bk,
                 const float* __restrict__ Wv, const float* __restrict__ bv,
                 const float* __restrict__ E,  const float* __restrict__ Wo)
{
    __shared__ __half Xs[128*ZP];  // X tile [s][e]
    __shared__ __half Ws[64*ZP];   // W tile [d][e]

    int which = blockIdx.y;
    if (which == 3) {
        for (int i = blockIdx.x * 256 + threadIdx.x; i < NE4 + NW4; i += 256*256) {
            if (i < NE4) {
                float4 x = reinterpret_cast<const float4*>(E)[i];
                uint2 u; u.x = h2u(x.x, x.y); u.y = h2u(x.z, x.w);
                reinterpret_cast<uint2*>(g_eh)[i] = u;
            } else {
                int j = i - NE4;
                float4 x = reinterpret_cast<const float4*>(Wo)[j];
                uint2 u; u.x = h2u(x.x, x.y); u.y = h2u(x.z, x.w);
                reinterpret_cast<uint2*>(g_wo)[j] = u;
            }
        }
        return;
    }

    const float* X = (which == 0) ? q  : (which == 1) ? k  : v;
    const float* W = (which == 0) ? Wq : (which == 1) ? Wk : Wv;
    const float* b = (which == 0) ? bq : (which == 1) ? bk : bv;
    __half*    Out = (which == 0) ? g_qh : (which == 1) ? g_kh : g_vh;
    const float scale = (which == 1) ? KSCALE : 1.0f;

    int bid = blockIdx.x;
    int st  = bid % (S/128);
    int h   = (bid / (S/128)) % H;
    int n   = bid / ((S/128) * H);
    int s0  = st * 128;
    int tid  = threadIdx.x;
    int lane = tid & 31;
    int wr   = tid >> 5;
    int lq   = lane >> 2;
    int lr   = lane & 3;
    int g8   = lane >> 3;
    int i8   = lane & 7;

    const int ar = (g8 & 1)*8 + i8;     // A ldmatrix row
    const int ac = (g8 >> 1)*8;
    const int nr = (g8 >> 1)*8 + i8;    // B ldmatrix row
    const int nc = (g8 & 1)*8;

    for (int t = tid; t < 128*16; t += 256) {
        int r = t >> 4, e4 = (t & 15) * 4;
        float4 x = *reinterpret_cast<const float4*>(X + (size_t)(n*S + s0 + r)*EMB + h*D + e4);
        uint2 ux; ux.x = h2u(x.x, x.y); ux.y = h2u(x.z, x.w);
        *reinterpret_cast<uint2*>(Xs + r*ZP + e4) = ux;
    }
    for (int t = tid; t < 64*16; t += 256) {
        int r = t >> 4, e4 = (t & 15) * 4;
        float4 w = *reinterpret_cast<const float4*>(W + (size_t)r*D + e4);
        uint2 uw; uw.x = h2u(w.x, w.y); uw.y = h2u(w.z, w.w);
        *reinterpret_cast<uint2*>(Ws + r*ZP + e4) = uw;
    }
    __syncthreads();

    float acc[8][4];
#pragma unroll
    for (int nt = 0; nt < 8; nt++)
#pragma unroll
        for (int i = 0; i < 4; i++) acc[nt][i] = 0.f;

#pragma unroll
    for (int ks = 0; ks < 4; ks++) {
        uint32_t av[4];
        ldsm4(av, Xs + (wr*16 + ar)*ZP + ks*16 + ac);
#pragma unroll
        for (int nt2 = 0; nt2 < 4; nt2++) {
            uint32_t bb[4];
            ldsm4(bb, Ws + (nt2*16 + nr)*ZP + ks*16 + nc);
            mma16(acc[2*nt2],   av[0], av[1], av[2], av[3], bb[0], bb[1]);
            mma16(acc[2*nt2+1], av[0], av[1], av[2], av[3], bb[2], bb[3]);
        }
    }

    int row = s0 + wr*16 + lq;
    __half* op0 = Out + ((size_t)(n*H + h)*S + row)*D;
    __half* op1 = op0 + 8*D;
#pragma unroll
    for (int nt = 0; nt < 8; nt++) {
        int col = nt*8 + 2*lr;
        float2 bb = *reinterpret_cast<const float2*>(b + col);
        uint32_t lo = h2u((acc[nt][0] + bb.x)*scale, (acc[nt][1] + bb.y)*scale);
        uint32_t hi = h2u((acc[nt][2] + bb.x)*scale, (acc[nt][3] + bb.y)*scale);
        *reinterpret_cast<uint32_t*>(op0 + col) = lo;
        *reinterpret_cast<uint32_t*>(op1 + col) = hi;
    }
}

// ---------------------------------------------------------------------------
// attn staging helpers (256 threads)
// ---------------------------------------------------------------------------
__device__ __forceinline__ void stage_kv(
    int jt, int tid, int q0,
    const __half* Kh, const __half* Vh, __half* Ksm, __half* Vsm)
{
    int j0 = jt * 64, buf = jt & 1;
    {
        __half* Vd = Vsm + buf*KTILE;
        const __half* src = Vh + (size_t)j0*D;
#pragma unroll
        for (int t = tid; t < 512; t += 256) {
            int r = t >> 3, c = t & 7;
            cpa16(Vd + r*VP + c*8, src + r*D + c*8);
        }
    }
    if (j0 >= q0) {
        __half* Kd = Ksm + buf*KTILE;
        const __half* src = Kh + (size_t)j0*D;
#pragma unroll
        for (int t = tid; t < 512; t += 256) {
            int r = t >> 3, c = t & 7;
            cpa16(Kd + r*KP + c*8, src + r*D + c*8);
        }
    }
}

__device__ __forceinline__ void stage_e(int c, int tid, int l_origin, __half* Esm)
{
    int slot = (c & 3) * 64;
#pragma unroll
    for (int t = tid; t < 512; t += 256) {
        int r = t >> 3, cc = t & 7;
        int l = l_origin + c*64 + r;
        const __half* src = (l < S) ? (g_eh + (size_t)l*D + cc*8) : g_eh;
        cpa16z(Esm + (slot + r)*EP + cc*8, src, (l < S) ? 16 : 0);
    }
}

// ---------------------------------------------------------------------------
// Kernel 2: fused attention (software-pipelined mma loops; proven R16).
// ---------------------------------------------------------------------------
__global__ __launch_bounds__(256, 2)
void attn_kernel()
{
    extern __shared__ __half smh[];
    __half* Ksm = smh;                     // 2 x [64][KP]
    __half* Vsm = Ksm + 2*KTILE;           // 2 x [64][VP]
    __half* Esm = Vsm + 2*KTILE;           // [256][EP] ring (4 chunks)
    __half* Psh = Esm + ERING*EP;          // [128][PP]

    int bid = blockIdx.x;
    int qtb = bid % NTB;
    int h   = (bid / NTB) % H;
    int n   = bid / (NTB * H);
    int q0  = qtb * BQB;
    int tid  = threadIdx.x;
    int lane = tid & 31;
    int wr   = tid >> 5;
    int lq   = lane >> 2;
    int lr   = lane & 3;
    int g8   = lane >> 3;
    int i8   = lane & 7;

    const int nr = (g8 >> 1)*8 + i8;    // non-trans B row
    const int nc = (g8 & 1)*8;          // non-trans B col
    const int jr = (g8 & 1)*8 + i8;     // trans (V) row
    const int dc = (g8 >> 1)*8;         // trans (V) col
    const int ar = (g8 & 1)*8 + i8;     // A row (Psh)
    const int ac = (g8 >> 1)*8;         // A col

    const __half* Qh = g_qh + (size_t)(n*H + h)*S*D;
    const __half* Kh = g_kh + (size_t)(n*H + h)*S*D;
    const __half* Vh = g_vh + (size_t)(n*H + h)*S*D;

    const int grpB  = (wr >= 4);
    const int q0w   = q0 + grpB*64;        // warp's 64-row tile base
    const int qtw   = q0w >> 6;            // transition j-tile
    const int w16   = (wr & 3) * 16;
    const int rloc  = w16 + lq;            // row local to warp's 64-group
    const int rblk  = wr*16 + lq;          // row local to 128-block
    const int ilo   = q0 + rblk;           // global row (and +8)
    const int l_origin = S - 128 - q0;
    const int bandlo = 48 - w16, bandhi = 126 - w16;

    // Q fragments, resident
    uint32_t qa[4][4];
#pragma unroll
    for (int ks = 0; ks < 4; ks++) {
        const __half* qb = Qh + (size_t)ilo*D + ks*16 + 2*lr;
        qa[ks][0] = *reinterpret_cast<const uint32_t*>(qb);
        qa[ks][1] = *reinterpret_cast<const uint32_t*>(qb + 8*D);
        qa[ks][2] = *reinterpret_cast<const uint32_t*>(qb + 8);
        qa[ks][3] = *reinterpret_cast<const uint32_t*>(qb + 8*D + 8);
    }

    float acc[8][4];
#pragma unroll
    for (int nt = 0; nt < 8; nt++)
#pragma unroll
        for (int i = 0; i < 4; i++) acc[nt][i] = 0.f;

    float s0 = 0.f, s1 = 0.f;   // lane-local partials; reduced in epilogue

    // ---- pipeline prologue: tile 0 K/V + E chunks 0,1,2 ----
    stage_kv(0, tid, q0, Kh, Vh, Ksm, Vsm);
    stage_e(0, tid, l_origin, Esm);
    stage_e(1, tid, l_origin, Esm);
    stage_e(2, tid, l_origin, Esm);
    CP_COMMIT();

    for (int jt = 0; jt < NTJ; jt++) {
        int j0 = jt * 64;

        if (jt + 1 < NTJ) {
            stage_kv(jt + 1, tid, q0, Kh, Vh, Ksm, Vsm);
            if (jt < 2*qtb) stage_e(jt + 3, tid, l_origin, Esm);
        }
        CP_COMMIT();
        CP_WAIT1();
        __syncthreads();   // tile jt data visible to all threads

        const __half* Kt = Ksm + (jt & 1)*KTILE;
        const __half* Vt = Vsm + (jt & 1)*KTILE;

        // ================= doR (first: transition spill precedes doP) ======
        if (j0 <= q0w) {
            int bc   = jt + 1 - grpB;          // base E chunk for this warp
            int dq   = q0w - j0;
            int base = (bc & 3) * 64;

#pragma unroll
            for (int cb = 0; cb < 8; cb++) {
                if (cb*16 + 15 < bandlo || cb*16 > bandhi) continue;
                int rowb = base + cb*16; if (rowb >= ERING) rowb -= ERING;
                const __half* Eb = Esm + (rowb + nr)*EP + nc;
                float qeA[4] = {0.f,0.f,0.f,0.f};
                float qeB[4] = {0.f,0.f,0.f,0.f};
                uint32_t eb[2][4];
                ldsm4(eb[0], Eb);
#pragma unroll
                for (int ks = 0; ks < 4; ks++) {
                    if (ks < 3) ldsm4(eb[(ks+1)&1], Eb + (ks+1)*16);
                    mma16(qeA, qa[ks][0], qa[ks][1], qa[ks][2], qa[ks][3],
                          eb[ks&1][0], eb[ks&1][1]);
                    mma16(qeB, qa[ks][0], qa[ks][1], qa[ks][2], qa[ks][3],
                          eb[ks&1][2], eb[ks&1][3]);
                }
#pragma unroll
                for (int hb = 0; hb < 2; hb++) {
                    float* qv = hb ? qeB : qeA;
                    int rr  = cb*16 + hb*8 + 2*lr;
                    int cjA = rr - 63 + rloc;
                    int cjB = cjA + 8;
                    if (cjA >= 0 && cjA < 64)
                        Psh[rblk*PP + cjA] =
                            __float2half((cjA <= dq + rloc) ? qv[0] : 0.f);
                    if (cjA + 1 >= 0 && cjA + 1 < 64)
                        Psh[rblk*PP + cjA + 1] =
                            __float2half((cjA + 1 <= dq + rloc) ? qv[1] : 0.f);
                    if (cjB >= 0 && cjB < 64)
                        Psh[(rblk + 8)*PP + cjB] =
                            __float2half((cjB <= dq + rloc + 8) ? qv[2] : 0.f);
                    if (cjB + 1 >= 0 && cjB + 1 < 64)
                        Psh[(rblk + 8)*PP + cjB + 1] =
                            __float2half((cjB + 1 <= dq + rloc + 8) ? qv[3] : 0.f);
                }
            }
            __syncwarp();

            // acc += R @ V  (pipelined)
            {
                const __half* Pb = Psh + (wr*16 + ar)*PP + ac;
                uint32_t av[2][4], rb[2][4];
                ldsm4(av[0], Pb);
                ldsm4t(rb[0], Vt + jr*VP + dc);
#pragma unroll
                for (int i = 0; i < 16; i++) {
                    int ksv = i >> 2, nt2 = i & 3;
                    if (i < 15) {
                        int j = i + 1;
                        ldsm4t(rb[j & 1],
                               Vt + ((j >> 2)*16 + jr)*VP + (j & 3)*16 + dc);
                    }
                    if (nt2 == 0 && ksv < 3)
                        ldsm4(av[(ksv + 1) & 1], Pb + (ksv + 1)*16);
                    uint32_t* a = av[ksv & 1];
                    mma16(acc[2*nt2],   a[0], a[1], a[2], a[3],
                          rb[i&1][0], rb[i&1][1]);
                    mma16(acc[2*nt2+1], a[0], a[1], a[2], a[3],
                          rb[i&1][2], rb[i&1][3]);
                }
            }

            if (jt == qtw) {
                // spill finished R-part, recycle registers for P-part
                float* rp0 = g_racc + ((size_t)n*S + ilo    )*EMB + h*D;
                float* rp1 = g_racc + ((size_t)n*S + ilo + 8)*EMB + h*D;
#pragma unroll
                for (int nt = 0; nt < 8; nt++) {
                    int col = nt*8 + 2*lr;
                    *reinterpret_cast<float2*>(rp0 + col) =
                        make_float2(acc[nt][0], acc[nt][1]);
                    *reinterpret_cast<float2*>(rp1 + col) =
                        make_float2(acc[nt][2], acc[nt][3]);
                    acc[nt][0] = 0.f; acc[nt][1] = 0.f;
                    acc[nt][2] = 0.f; acc[nt][3] = 0.f;
                }
            }
        }

        // ================= doP =============================================
        if (j0 >= q0w) {
            // ---- scores (pipelined ldsm->mma) ----
            float sc[8][4];
#pragma unroll
            for (int nt = 0; nt < 8; nt++)
#pragma unroll
                for (int i = 0; i < 4; i++) sc[nt][i] = 0.f;
            {
                uint32_t kb[2][4];
                ldsm4(kb[0], Kt + nr*KP + nc);
#pragma unroll
                for (int i = 0; i < 16; i++) {
                    int ks = i >> 2, nt2 = i & 3;
                    if (i < 15) {
                        int j = i + 1;
                        ldsm4(kb[j & 1],
                              Kt + ((j & 3)*16 + nr)*KP + (j >> 2)*16 + nc);
                    }
                    mma16(sc[2*nt2],   qa[ks][0], qa[ks][1], qa[ks][2], qa[ks][3],
                          kb[i&1][0], kb[i&1][1]);
                    mma16(sc[2*nt2+1], qa[ks][0], qa[ks][1], qa[ks][2], qa[ks][3],
                          kb[i&1][2], kb[i&1][3]);
                }
            }

            // mask only on the diagonal tile
            if (j0 == q0w) {
#pragma unroll
                for (int nt = 0; nt < 8; nt++) {
                    int jc = j0 + nt*8 + 2*lr;
                    if (jc     <= ilo    ) sc[nt][0] = -INFINITY;
                    if (jc + 1 <= ilo    ) sc[nt][1] = -INFINITY;
                    if (jc     <= ilo + 8) sc[nt][2] = -INFINITY;
                    if (jc + 1 <= ilo + 8) sc[nt][3] = -INFINITY;
                }
            }

            // issue first V fragment BEFORE the exp2 chain (overlap LDS/MUFU)
            uint32_t vb[2][4];
            ldsm4t(vb[0], Vt + jr*VP + dc);

            // fixed-max softmax: p = exp2(score); lane-local denominators
            uint32_t ph0[8], ph1[8];
#pragma unroll
            for (int nt = 0; nt < 8; nt++) {
                float p0 = exp2f(sc[nt][0]);
                float p1 = exp2f(sc[nt][1]);
                float p2 = exp2f(sc[nt][2]);
                float p3 = exp2f(sc[nt][3]);
                s0 += p0 + p1;  s1 += p2 + p3;
                ph0[nt] = h2u(p0, p1);
                ph1[nt] = h2u(p2, p3);
            }

            // acc += P @ V (P from registers; V pipelined)
#pragma unroll
            for (int i = 0; i < 16; i++) {
                int ksv = i >> 2, nt2 = i & 3;
                if (i < 15) {
                    int j = i + 1;
                    ldsm4t(vb[j & 1],
                           Vt + ((j >> 2)*16 + jr)*VP + (j & 3)*16 + dc);
                }
                uint32_t a0 = ph0[2*ksv],   a1 = ph1[2*ksv];
                uint32_t a2 = ph0[2*ksv+1], a3 = ph1[2*ksv+1];
                mma16(acc[2*nt2],   a0, a1, a2, a3, vb[i&1][0], vb[i&1][1]);
                mma16(acc[2*nt2+1], a0, a1, a2, a3, vb[i&1][2], vb[i&1][3]);
            }
        }

        __syncthreads();   // all warps done with cur buffers before overwrite
    }

    // ---- epilogue ----
    s0 += __shfl_xor_sync(0xffffffffu, s0, 1);
    s0 += __shfl_xor_sync(0xffffffffu, s0, 2);
    s1 += __shfl_xor_sync(0xffffffffu, s1, 1);
    s1 += __shfl_xor_sync(0xffffffffu, s1, 2);
    float f0 = (ilo     == S-1) ? 0.f : 1.0f / s0;
    float f1 = (ilo + 8 == S-1) ? 0.f : 1.0f / s1;
    const float* rp0 = g_racc + ((size_t)n*S + ilo    )*EMB + h*D;
    const float* rp1 = g_racc + ((size_t)n*S + ilo + 8)*EMB + h*D;
#pragma unroll
    for (int nt = 0; nt < 8; nt++) {
        int col = nt*8 + 2*lr;
        float2 r0 = *reinterpret_cast<const float2*>(rp0 + col);
        float2 r1 = *reinterpret_cast<const float2*>(rp1 + col);
        uint32_t lo = h2u(acc[nt][0]*f0 + r0.x, acc[nt][1]*f0 + r0.y);
        uint32_t hi = h2u(acc[nt][2]*f1 + r1.x, acc[nt][3]*f1 + r1.y);
        *reinterpret_cast<uint32_t*>(g_z + ((size_t)n*S + ilo    )*EMB + h*D + col) = lo;
        *reinterpret_cast<uint32_t*>(g_z + ((size_t)n*S + ilo + 8)*EMB + h*D + col) = hi;
    }
}

// ---------------------------------------------------------------------------
// Kernel 2b: row S-1 uniform-softmax partials (finisher folded into outproj).
// ---------------------------------------------------------------------------
__global__ __launch_bounds__(256)
void vsum_part_kernel()
{
    __shared__ float sums[256];
    int blk   = blockIdx.x;          // nh*VSPLIT + split
    int nh    = blk / VSPLIT;
    int split = blk % VSPLIT;
    int tid = threadIdx.x;
    int d    = tid & 63;
    int part = tid >> 6;             // 4 parts x 64 rows
    const __half* Vp = g_vh + (size_t)nh*S*D
                     + ((size_t)split*256 + (size_t)part*64)*D + d;

    float s = 0.f;
#pragma unroll 1
    for (int j = 0; j < 64; j += 8) {
        float t0 = __half2float(Vp[(j+0)*D]);
        float t1 = __half2float(Vp[(j+1)*D]);
        float t2 = __half2float(Vp[(j+2)*D]);
        float t3 = __half2float(Vp[(j+3)*D]);
        float t4 = __half2float(Vp[(j+4)*D]);
        float t5 = __half2float(Vp[(j+5)*D]);
        float t6 = __half2float(Vp[(j+6)*D]);
        float t7 = __half2float(Vp[(j+7)*D]);
        s += ((t0 + t1) + (t2 + t3)) + ((t4 + t5) + (t6 + t7));
    }
    sums[tid] = s;
    __syncthreads();

    if (tid < 64) {
        float t = sums[tid] + sums[tid+64] + sums[tid+128] + sums[tid+192];
        g_vpart[(size_t)blk*D + tid] = t;
    }
}

// ---------------------------------------------------------------------------
// Kernel 3: out = z @ Wo.T + bo — fp16 tensor cores, cp.async k-pipeline.
// Blocks whose z-tile contains row S-1 patch the staged copy of local row
// 127 with the uniform-softmax correction (head index == kc since heads are
// 64 cols wide) — exactly what vsum_fin used to write into g_z.
// ---------------------------------------------------------------------------
__global__ __launch_bounds__(256)
void outproj_kernel(const float* __restrict__ bo, float* __restrict__ out)
{
    extern __shared__ __half smo[];
    __half* Zs = smo;                    // 2 x [128][ZP]
    __half* Ws = smo + 2*128*ZP;         // 2 x [64][ZP]

    int r0  = blockIdx.x * 128;
    int d0  = blockIdx.y * 64;
    int tid  = threadIdx.x;
    int lane = tid & 31;
    int wr   = tid >> 5;
    int lq   = lane >> 2;
    int lr   = lane & 3;
    int g8   = lane >> 3;
    int i8   = lane & 7;

    const int ar = (g8 & 1)*8 + i8;
    const int ac = (g8 >> 1)*8;
    const int nr = (g8 >> 1)*8 + i8;
    const int nc = (g8 & 1)*8;

    const bool fixrow = ((r0 & (S - 1)) == S - 128);  // tile contains row S-1
    const int  nbatch = r0 / S;

    float acc[8][4];
#pragma unroll
    for (int nt = 0; nt < 8; nt++)
#pragma unroll
        for (int i = 0; i < 4; i++) acc[nt][i] = 0.f;

    auto stage = [&](int kc) {
        int buf = kc & 1;
        int e0  = kc * 64;
        __half* Zd = Zs + buf*128*ZP;
        __half* Wd = Ws + buf*64*ZP;
#pragma unroll
        for (int t = tid; t < 1024; t += 256) {
            int r = t >> 3, c = t & 7;
            cpa16(Zd + r*ZP + c*8, g_z + (size_t)(r0 + r)*EMB + e0 + c*8);
        }
#pragma unroll
        for (int t = tid; t < 512; t += 256) {
            int r = t >> 3, c = t & 7;
            cpa16(Wd + r*ZP + c*8, g_wo + (size_t)(d0 + r)*EMB + e0 + c*8);
        }
    };

    stage(0);
    CP_COMMIT();

    for (int kc = 0; kc < 8; kc++) {
        if (kc + 1 < 8) stage(kc + 1);
        CP_COMMIT();
        CP_WAIT1();
        __syncthreads();   // chunk kc visible to all threads

        __half* Zb = Zs + (kc & 1)*128*ZP;
        const __half* Wb = Ws + (kc & 1)*64*ZP;

        if (fixrow) {
            // patch staged row 127 (= z row S-1) for head kc
            if (tid < 64) {
                float t = 0.f;
#pragma unroll
                for (int p = 0; p < VSPLIT; p++)
                    t += g_vpart[((size_t)(nbatch*H + kc)*VSPLIT + p)*D + tid];
                __half* zp = Zb + 127*ZP + tid;
                *zp = __float2half(__half2float(*zp) + t * (1.0f / (float)S));
            }
            __syncthreads();
        }

#pragma unroll
        for (int ks = 0; ks < 4; ks++) {
            uint32_t av[4];
            ldsm4(av, Zb + (wr*16 + ar)*ZP + ks*16 + ac);
#pragma unroll
            for (int nt2 = 0; nt2 < 4; nt2++) {
                uint32_t b[4];
                ldsm4(b, Wb + (nt2*16 + nr)*ZP + ks*16 + nc);
                mma16(acc[2*nt2],   av[0], av[1], av[2], av[3], b[0], b[1]);
                mma16(acc[2*nt2+1], av[0], av[1], av[2], av[3], b[2], b[3]);
            }
        }
        __syncthreads();   // reads done before next overwrite of this buffer
    }

    int row = r0 + wr*16 + lq;
#pragma unroll
    for (int nt = 0; nt < 8; nt++) {
        int col = d0 + nt*8 + 2*lr;
        float2 bb = *reinterpret_cast<const float2*>(bo + col);
        float2 lo = make_float2(acc[nt][0] + bb.x, acc[nt][1] + bb.y);
        float2 hi = make_float2(acc[nt][2] + bb.x, acc[nt][3] + bb.y);
        *reinterpret_cast<float2*>(out + (size_t)row*EMB + col) = lo;
        *reinterpret_cast<float2*>(out + (size_t)(row + 8)*EMB + col) = hi;
    }
}

// ---------------------------------------------------------------------------
extern "C" void kernel_launch(void* const* d_in, const int* in_sizes, int n_in,
                              void* d_out, int out_size)
{
    const float* v  = (const float*)d_in[0];
    const float* k  = (const float*)d_in[1];
    const float* q  = (const float*)d_in[2];
    const float* Wv = (const float*)d_in[3];
    const float* bv = (const float*)d_in[4];
    const float* Wk = (const float*)d_in[5];
    const float* bk = (const float*)d_in[6];
    const float* Wq = (const float*)d_in[7];
    const float* bq = (const float*)d_in[8];
    const float* E  = (const float*)d_in[9];
    const float* Wo = (const float*)d_in[10];
    const float* bo = (const float*)d_in[11];
    float* out = (float*)d_out;

    dim3 gp(NB*H*(S/128), 4);   // y=0..2: q/k/v proj, y=3: E/Wo convert
    proj_kernel<<<gp, 256>>>(q, k, v, Wq, bq, Wk, bk, Wv, bv, E, Wo);

    vsum_part_kernel<<<NB*H*VSPLIT, 256>>>();

    size_t smem = (size_t)(2*KTILE + 2*KTILE + ERING*EP + 128*PP) * sizeof(__half);
    cudaFuncSetAttribute(attn_kernel,
                         cudaFuncAttributeMaxDynamicSharedMemorySize,
                         (int)smem);
    attn_kernel<<<NB*H*NTB, 256, smem>>>();

    size_t smemo = (size_t)(2*128*ZP + 2*64*ZP) * sizeof(__half);
    cudaFuncSetAttribute(outproj_kernel,
                         cudaFuncAttributeMaxDynamicSharedMemorySize,
                         (int)smemo);
    dim3 go(NB*S/128, EMB/64);
    outproj_kernel<<<go, 256, smemo>>>(bo, out);
}